// round 1
// baseline (speedup 1.0000x reference)
#include <cuda_runtime.h>
#include <cuda_bf16.h>
#include <cstdint>

#define TOKENS 8192
#define DMODEL 2048
#define DFF    8192

// ---------------- device scratch (no allocations allowed) ----------------
struct Scalars {
    unsigned int absmax_x;   // float bits, values >= 0
    unsigned int absmax_h;
    double       sum_w1;
    double       sum_w2;
};

__device__ Scalars        g_sc;
__device__ __nv_bfloat16  g_qx [(size_t)TOKENS * DMODEL];   // 32 MB
__device__ __nv_bfloat16  g_w1t[(size_t)DFF    * DMODEL];   // 32 MB
__device__ float          g_h  [(size_t)TOKENS * DFF];      // 256 MB
__device__ __nv_bfloat16  g_qh [(size_t)TOKENS * DFF];      // 128 MB
__device__ __nv_bfloat16  g_w2t[(size_t)DMODEL * DFF];      // 32 MB

// ---------------- small helpers ----------------
__device__ __forceinline__ float gelu_exact(float v) {
    return 0.5f * v * (1.0f + erff(v * 0.70710678118654752440f));
}

__device__ __forceinline__ unsigned smem_u32(const void* p) {
    return (unsigned)__cvta_generic_to_shared(p);
}

// ---------------- reduction kernels ----------------
__global__ void k_absmax(const float4* __restrict__ p, int n4,
                         unsigned int* __restrict__ out) {
    float m = 0.f;
    for (int i = blockIdx.x * blockDim.x + threadIdx.x; i < n4;
         i += gridDim.x * blockDim.x) {
        float4 v = p[i];
        m = fmaxf(m, fmaxf(fmaxf(fabsf(v.x), fabsf(v.y)),
                           fmaxf(fabsf(v.z), fabsf(v.w))));
    }
    #pragma unroll
    for (int o = 16; o; o >>= 1) m = fmaxf(m, __shfl_xor_sync(0xffffffffu, m, o));
    __shared__ float s[32];
    if ((threadIdx.x & 31) == 0) s[threadIdx.x >> 5] = m;
    __syncthreads();
    if (threadIdx.x < 32) {
        float v = (threadIdx.x < (blockDim.x >> 5)) ? s[threadIdx.x] : 0.f;
        #pragma unroll
        for (int o = 16; o; o >>= 1) v = fmaxf(v, __shfl_xor_sync(0xffffffffu, v, o));
        if (threadIdx.x == 0) atomicMax(out, __float_as_uint(v));
    }
}

__global__ void k_abssum(const float4* __restrict__ p, int n4,
                         double* __restrict__ out) {
    double s = 0.0;
    for (int i = blockIdx.x * blockDim.x + threadIdx.x; i < n4;
         i += gridDim.x * blockDim.x) {
        float4 v = p[i];
        s += (double)fabsf(v.x) + (double)fabsf(v.y) +
             (double)fabsf(v.z) + (double)fabsf(v.w);
    }
    #pragma unroll
    for (int o = 16; o; o >>= 1) s += __shfl_xor_sync(0xffffffffu, s, o);
    __shared__ double sd[32];
    if ((threadIdx.x & 31) == 0) sd[threadIdx.x >> 5] = s;
    __syncthreads();
    if (threadIdx.x < 32) {
        double v = (threadIdx.x < (blockDim.x >> 5)) ? sd[threadIdx.x] : 0.0;
        #pragma unroll
        for (int o = 16; o; o >>= 1) v += __shfl_xor_sync(0xffffffffu, v, o);
        if (threadIdx.x == 0) atomicAdd(out, v);
    }
}

// ---------------- quantize / ternarize ----------------
// q = round_half_even(clamp(x * (127/max), -127, 127)) stored as bf16 (exact ints)
__global__ void k_quant(const float4* __restrict__ in, uint2* __restrict__ out,
                        int n4, const unsigned int* __restrict__ mxp) {
    float s = 127.0f / __uint_as_float(*mxp);
    for (int i = blockIdx.x * blockDim.x + threadIdx.x; i < n4;
         i += gridDim.x * blockDim.x) {
        float4 v = in[i];
        float q0 = rintf(fminf(fmaxf(v.x * s, -127.f), 127.f));
        float q1 = rintf(fminf(fmaxf(v.y * s, -127.f), 127.f));
        float q2 = rintf(fminf(fmaxf(v.z * s, -127.f), 127.f));
        float q3 = rintf(fminf(fmaxf(v.w * s, -127.f), 127.f));
        __nv_bfloat162 p0 = __floats2bfloat162_rn(q0, q1);
        __nv_bfloat162 p1 = __floats2bfloat162_rn(q2, q3);
        uint2 o;
        o.x = *reinterpret_cast<unsigned int*>(&p0);
        o.y = *reinterpret_cast<unsigned int*>(&p1);
        out[i] = o;
    }
}

// t = round_half_even(clamp(w/scale, -1, 1)) in {-1,0,1}, scale = mean|W|
__global__ void k_tern(const float4* __restrict__ in, uint2* __restrict__ out,
                       int n4, const double* __restrict__ sump) {
    float scale = (float)(*sump * (1.0 / 16777216.0));
    for (int i = blockIdx.x * blockDim.x + threadIdx.x; i < n4;
         i += gridDim.x * blockDim.x) {
        float4 v = in[i];
        float q0 = rintf(fminf(fmaxf(v.x / scale, -1.f), 1.f));
        float q1 = rintf(fminf(fmaxf(v.y / scale, -1.f), 1.f));
        float q2 = rintf(fminf(fmaxf(v.z / scale, -1.f), 1.f));
        float q3 = rintf(fminf(fmaxf(v.w / scale, -1.f), 1.f));
        __nv_bfloat162 p0 = __floats2bfloat162_rn(q0, q1);
        __nv_bfloat162 p1 = __floats2bfloat162_rn(q2, q3);
        uint2 o;
        o.x = *reinterpret_cast<unsigned int*>(&p0);
        o.y = *reinterpret_cast<unsigned int*>(&p1);
        out[i] = o;
    }
}

// ---------------- GEMM: C[M,N] = A[M,K] @ B[N,K]^T, bf16 in / fp32 acc ----------------
// BM=128, BN=128, BK=32, 256 threads (8 warps, 2x4 warp grid, warp tile 64x32)
#define BKT 32
#define SSTRIDE 40   // bf16 elems per smem row (128B data + 16B pad)

template <int EPI>   // EPI==1: *c + bias, GELU, store h, track absmax  | EPI==0: *c + bias
__global__ void __launch_bounds__(256) k_gemm(
    const __nv_bfloat16* __restrict__ A,
    const __nv_bfloat16* __restrict__ B,
    const float* __restrict__ bias,
    float* __restrict__ C,
    int M, int N, int K,
    const double* __restrict__ sump,
    const unsigned int* __restrict__ mxp,
    unsigned int* __restrict__ amax_out)
{
    __shared__ __nv_bfloat16 sA[2][128 * SSTRIDE];
    __shared__ __nv_bfloat16 sB[2][128 * SSTRIDE];
    __shared__ float sred[8];

    const int tid  = threadIdx.x;
    const int wid  = tid >> 5;
    const int lane = tid & 31;
    const int bm = blockIdx.y * 128;
    const int bn = blockIdx.x * 128;

    const float cf = (float)(*sump * (1.0 / 16777216.0)) *
                     (__uint_as_float(*mxp) / 127.0f);

    const __nv_bfloat16* gA = A + (size_t)bm * K;
    const __nv_bfloat16* gB = B + (size_t)bn * K;

    auto issue = [&](int kt, int buf) {
        int k0 = kt * BKT;
        #pragma unroll
        for (int i = 0; i < 2; i++) {
            int c = tid + i * 256;
            int row = c >> 2;
            int col = (c & 3) * 8;
            unsigned da = smem_u32(&sA[buf][row * SSTRIDE + col]);
            const __nv_bfloat16* pa = gA + (size_t)row * K + k0 + col;
            asm volatile("cp.async.cg.shared.global [%0], [%1], 16;\n" ::"r"(da), "l"(pa));
            unsigned db = smem_u32(&sB[buf][row * SSTRIDE + col]);
            const __nv_bfloat16* pb = gB + (size_t)row * K + k0 + col;
            asm volatile("cp.async.cg.shared.global [%0], [%1], 16;\n" ::"r"(db), "l"(pb));
        }
        asm volatile("cp.async.commit_group;\n");
    };

    float acc[4][4][4];
    #pragma unroll
    for (int a = 0; a < 4; a++)
        #pragma unroll
        for (int b = 0; b < 4; b++)
            #pragma unroll
            for (int c = 0; c < 4; c++) acc[a][b][c] = 0.f;

    const int warpM = wid & 1;
    const int warpN = wid >> 1;
    const int mbase = warpM * 64;
    const int nbase = warpN * 32;

    const int kTiles = K / BKT;
    issue(0, 0);

    for (int kt = 0; kt < kTiles; kt++) {
        int buf = kt & 1;
        if (kt + 1 < kTiles) issue(kt + 1, buf ^ 1);
        else asm volatile("cp.async.commit_group;\n");
        asm volatile("cp.async.wait_group 1;\n");
        __syncthreads();

        #pragma unroll
        for (int ks = 0; ks < 2; ks++) {
            const int k0 = ks * 16;
            uint32_t af[4][4], bfrag[2][4];
            #pragma unroll
            for (int mt = 0; mt < 4; mt++) {
                int r = mbase + mt * 16 + (lane & 15);
                int cc = k0 + ((lane >> 4) << 3);
                unsigned addr = smem_u32(&sA[buf][r * SSTRIDE + cc]);
                asm volatile(
                    "ldmatrix.sync.aligned.m8n8.x4.shared.b16 {%0,%1,%2,%3}, [%4];"
                    : "=r"(af[mt][0]), "=r"(af[mt][1]), "=r"(af[mt][2]), "=r"(af[mt][3])
                    : "r"(addr));
            }
            #pragma unroll
            for (int np = 0; np < 2; np++) {
                int r  = nbase + np * 16 + (lane & 7) + ((lane >> 4) << 3);
                int cc = k0 + (((lane >> 3) & 1) << 3);
                unsigned addr = smem_u32(&sB[buf][r * SSTRIDE + cc]);
                asm volatile(
                    "ldmatrix.sync.aligned.m8n8.x4.shared.b16 {%0,%1,%2,%3}, [%4];"
                    : "=r"(bfrag[np][0]), "=r"(bfrag[np][1]), "=r"(bfrag[np][2]), "=r"(bfrag[np][3])
                    : "r"(addr));
            }
            #pragma unroll
            for (int mt = 0; mt < 4; mt++)
                #pragma unroll
                for (int nt = 0; nt < 4; nt++) {
                    uint32_t b0 = bfrag[nt >> 1][(nt & 1) * 2 + 0];
                    uint32_t b1 = bfrag[nt >> 1][(nt & 1) * 2 + 1];
                    asm volatile(
                        "mma.sync.aligned.m16n8k16.row.col.f32.bf16.bf16.f32 "
                        "{%0,%1,%2,%3}, {%4,%5,%6,%7}, {%8,%9}, {%0,%1,%2,%3};"
                        : "+f"(acc[mt][nt][0]), "+f"(acc[mt][nt][1]),
                          "+f"(acc[mt][nt][2]), "+f"(acc[mt][nt][3])
                        : "r"(af[mt][0]), "r"(af[mt][1]), "r"(af[mt][2]), "r"(af[mt][3]),
                          "r"(b0), "r"(b1));
                }
        }
        __syncthreads();
    }

    // ---------------- epilogue ----------------
    const int gid = lane >> 2;
    const int tig = lane & 3;
    float amax_local = 0.f;

    #pragma unroll
    for (int mt = 0; mt < 4; mt++) {
        #pragma unroll
        for (int nt = 0; nt < 4; nt++) {
            int row0 = bm + mbase + mt * 16 + gid;
            int col0 = bn + nbase + nt * 8 + tig * 2;
            float bv0 = bias[col0];
            float bv1 = bias[col0 + 1];
            #pragma unroll
            for (int hh = 0; hh < 2; hh++) {
                int row = row0 + hh * 8;
                float v0 = acc[mt][nt][hh * 2 + 0] * cf + bv0;
                float v1 = acc[mt][nt][hh * 2 + 1] * cf + bv1;
                if (EPI == 1) {
                    v0 = gelu_exact(v0);
                    v1 = gelu_exact(v1);
                    amax_local = fmaxf(amax_local, fmaxf(fabsf(v0), fabsf(v1)));
                }
                float2 st = make_float2(v0, v1);
                *reinterpret_cast<float2*>(&C[(size_t)row * N + col0]) = st;
            }
        }
    }

    if (EPI == 1) {
        #pragma unroll
        for (int o = 16; o; o >>= 1)
            amax_local = fmaxf(amax_local, __shfl_xor_sync(0xffffffffu, amax_local, o));
        if (lane == 0) sred[wid] = amax_local;
        __syncthreads();
        if (tid == 0) {
            float m = sred[0];
            #pragma unroll
            for (int i = 1; i < 8; i++) m = fmaxf(m, sred[i]);
            atomicMax(amax_out, __float_as_uint(m));
        }
    }
}

// ---------------- launch ----------------
extern "C" void kernel_launch(void* const* d_in, const int* in_sizes, int n_in,
                              void* d_out, int out_size) {
    const float* x  = (const float*)d_in[0];
    const float* W1 = (const float*)d_in[1];
    const float* b1 = (const float*)d_in[2];
    const float* W2 = (const float*)d_in[3];
    const float* b2 = (const float*)d_in[4];
    float* out = (float*)d_out;

    void *p_sc, *p_qx, *p_w1t, *p_h, *p_qh, *p_w2t;
    cudaGetSymbolAddress(&p_sc,  g_sc);
    cudaGetSymbolAddress(&p_qx,  g_qx);
    cudaGetSymbolAddress(&p_w1t, g_w1t);
    cudaGetSymbolAddress(&p_h,   g_h);
    cudaGetSymbolAddress(&p_qh,  g_qh);
    cudaGetSymbolAddress(&p_w2t, g_w2t);
    Scalars* sc = (Scalars*)p_sc;

    cudaMemsetAsync(p_sc, 0, sizeof(Scalars));

    const int n4_xw = TOKENS * DMODEL / 4;               // 4.19M
    const int n4_h  = (int)((size_t)TOKENS * DFF / 4);   // 16.7M

    k_absmax<<<2048, 256>>>((const float4*)x,  n4_xw, &sc->absmax_x);
    k_abssum<<<2048, 256>>>((const float4*)W1, n4_xw, &sc->sum_w1);
    k_abssum<<<2048, 256>>>((const float4*)W2, n4_xw, &sc->sum_w2);

    k_quant<<<2048, 256>>>((const float4*)x,  (uint2*)p_qx,  n4_xw, &sc->absmax_x);
    k_tern <<<2048, 256>>>((const float4*)W1, (uint2*)p_w1t, n4_xw, &sc->sum_w1);
    k_tern <<<2048, 256>>>((const float4*)W2, (uint2*)p_w2t, n4_xw, &sc->sum_w2);

    dim3 g1(DFF / 128, TOKENS / 128);      // (64, 64)
    k_gemm<1><<<g1, 256>>>((const __nv_bfloat16*)p_qx, (const __nv_bfloat16*)p_w1t,
                           b1, (float*)p_h, TOKENS, DFF, DMODEL,
                           &sc->sum_w1, &sc->absmax_x, &sc->absmax_h);

    k_quant<<<4096, 256>>>((const float4*)p_h, (uint2*)p_qh, n4_h, &sc->absmax_h);

    dim3 g2(DMODEL / 128, TOKENS / 128);   // (16, 64)
    k_gemm<0><<<g2, 256>>>((const __nv_bfloat16*)p_qh, (const __nv_bfloat16*)p_w2t,
                           b2, out, TOKENS, DMODEL, DFF,
                           &sc->sum_w2, &sc->absmax_h, nullptr);
}